// round 15
// baseline (speedup 1.0000x reference)
#include <cuda_runtime.h>
#include <cuda_fp16.h>
#include <cuda_fp8.h>
#include <cstdint>

// Problem constants
#define BATCH 2048
#define FEAT  2048
#define NKERN 128
#define NDIM  16
#define NCOL  (NKERN * NDIM)   // 2048

// Quantization scales: x*4, W*16 -> product 64x, undone in epilogue.
#define XSCALE 4.0f
#define WSCALE 16.0f
#define INV_SCALE (1.0f / 64.0f)

// ---------------------------------------------------------------------------
// Scratch (__device__ globals; no allocations allowed)
// ---------------------------------------------------------------------------
__device__ uint8_t g_x8[(size_t)BATCH * FEAT];   // 4 MB  x*4  e4m3 [B][F]
__device__ uint8_t g_w8[(size_t)NCOL * FEAT];    // 4 MB  W^T*16 e4m3 [N][F]
__device__ __half  g_Mh[(size_t)BATCH * NCOL];   // 8 MB  M in fp16

__device__ __forceinline__ uint32_t pack_fp8x4(float a, float b, float c, float d) {
    __nv_fp8x2_storage_t lo =
        __nv_cvt_float2_to_fp8x2(make_float2(a, b), __NV_SATFINITE, __NV_E4M3);
    __nv_fp8x2_storage_t hi =
        __nv_cvt_float2_to_fp8x2(make_float2(c, d), __NV_SATFINITE, __NV_E4M3);
    return (uint32_t)lo | ((uint32_t)hi << 16);
}

// ---------------------------------------------------------------------------
// Kernel 1a: x fp32 -> e4m3 (x*4), 16 elems/thread, LDG.128/STG.128
// ---------------------------------------------------------------------------
__global__ __launch_bounds__(256) void cvt_x_kernel(const float* __restrict__ x) {
    const int idx = blockIdx.x * blockDim.x + threadIdx.x;   // 0..262143
    const float4* fx = reinterpret_cast<const float4*>(x);
    const float4 v0 = fx[4 * idx + 0];
    const float4 v1 = fx[4 * idx + 1];
    const float4 v2 = fx[4 * idx + 2];
    const float4 v3 = fx[4 * idx + 3];
    uint4 u;
    u.x = pack_fp8x4(v0.x * XSCALE, v0.y * XSCALE, v0.z * XSCALE, v0.w * XSCALE);
    u.y = pack_fp8x4(v1.x * XSCALE, v1.y * XSCALE, v1.z * XSCALE, v1.w * XSCALE);
    u.z = pack_fp8x4(v2.x * XSCALE, v2.y * XSCALE, v2.z * XSCALE, v2.w * XSCALE);
    u.w = pack_fp8x4(v3.x * XSCALE, v3.y * XSCALE, v3.z * XSCALE, v3.w * XSCALE);
    reinterpret_cast<uint4*>(g_x8)[idx] = u;
}

// ---------------------------------------------------------------------------
// Kernel 1b: W fp32 [F][N] -> e4m3 transposed g_w8 [N][F] (W*16).
// Tile 128(f) x 32(n); smem transpose; 16B coalesced fp8 stores.
// ---------------------------------------------------------------------------
__global__ __launch_bounds__(256) void cvt_wt_kernel(const float* __restrict__ W) {
    __shared__ float tile[32][129];   // [n][f], pad -> conflict-free
    const int bn = blockIdx.x * 32;    // output-col block of W
    const int bk = blockIdx.y * 128;   // feature block
    const int tid = threadIdx.x;

    // Load 128x32 block of W (scaled), transposed into tile[n][f]
#pragma unroll
    for (int i = 0; i < 16; i++) {
        int li = tid + i * 256;        // 0..4095
        int f  = li >> 5;              // 0..127
        int n  = li & 31;
        tile[n][f] = W[(size_t)(bk + f) * NCOL + bn + n] * WSCALE;
    }
    __syncthreads();

    // Each thread emits 16 consecutive F-bytes of one N-row
    const int n = tid >> 3;            // 0..31
    const int c = (tid & 7) * 16;      // 0..112
    uint4 u;
    u.x = pack_fp8x4(tile[n][c+0],  tile[n][c+1],  tile[n][c+2],  tile[n][c+3]);
    u.y = pack_fp8x4(tile[n][c+4],  tile[n][c+5],  tile[n][c+6],  tile[n][c+7]);
    u.z = pack_fp8x4(tile[n][c+8],  tile[n][c+9],  tile[n][c+10], tile[n][c+11]);
    u.w = pack_fp8x4(tile[n][c+12], tile[n][c+13], tile[n][c+14], tile[n][c+15]);
    *reinterpret_cast<uint4*>(&g_w8[(size_t)(bn + n) * FEAT + bk + c]) = u;
}

// ---------------------------------------------------------------------------
// Kernel 2: fp8 (e4m3) tensor-core GEMM, fp32 accumulate, K=32 per mma
// (halves instruction count vs f16 k16 -> attacks the measured issue-rate
// wall). Tile BM=128, BN=128, BK=64 fp8, 3-stage cp.async, 1 barrier/iter.
// A [m][k] row-major, B [n][k] k-contiguous (W pre-transposed).
// Fragments via ldmatrix.b16 on byte-pair-packed tiles (layout coincides).
// ---------------------------------------------------------------------------
#define BM   128
#define BN   128
#define BKT  64          // fp8 elements = 64 bytes per row
#define RSTRIDE 80       // row stride bytes (64 + 16 pad): 20-word -> conflict-free
#define NSTAGE 3

#define A_STAGE_BYTES (BM * RSTRIDE)   // 10240
#define B_STAGE_BYTES (BN * RSTRIDE)   // 10240
#define GEMM_SMEM (NSTAGE * (A_STAGE_BYTES + B_STAGE_BYTES))  // 61440

__device__ __forceinline__ uint32_t smem_u32(const void* p) {
    uint32_t a;
    asm("{ .reg .u64 t; cvta.to.shared.u64 t, %1; cvt.u32.u64 %0, t; }"
        : "=r"(a) : "l"(p));
    return a;
}

__device__ __forceinline__ void cp_async16(uint32_t smem, const void* gmem) {
    asm volatile("cp.async.cg.shared.global [%0], [%1], 16;\n"
                 :: "r"(smem), "l"(gmem));
}
#define CP_COMMIT()  asm volatile("cp.async.commit_group;\n" ::: "memory")
#define CP_WAIT1()   asm volatile("cp.async.wait_group 1;\n" ::: "memory")

__global__ __launch_bounds__(256) void gemm_kernel() {
    extern __shared__ char smem_raw[];

    const int tid  = threadIdx.x;
    const int warp = tid >> 5;
    const int lane = tid & 31;
    const int wm   = (warp & 3) * 32;   // warp row offset
    const int wn   = (warp >> 2) * 64;  // warp col offset
    const int bm   = blockIdx.y * BM;
    const int bn   = blockIdx.x * BN;

    const uint32_t a_smem0 = smem_u32(smem_raw);
    const uint32_t b_smem0 = a_smem0 + NSTAGE * A_STAGE_BYTES;

    // Loader coords: 512 16B-chunks per tile, 2 per thread
    const int lr = tid >> 2;            // row 0..63 (x2 via +64)
    const int lc = (tid & 3) * 16;      // byte col

    float acc[2][8][4];
#pragma unroll
    for (int mt = 0; mt < 2; mt++)
#pragma unroll
        for (int nt = 0; nt < 8; nt++)
#pragma unroll
            for (int q = 0; q < 4; q++) acc[mt][nt][q] = 0.0f;

    auto load_tiles = [&](int k0, int s) {
        const uint32_t abase = a_smem0 + s * A_STAGE_BYTES;
        const uint32_t bbase = b_smem0 + s * B_STAGE_BYTES;
        cp_async16(abase + (uint32_t)(lr * RSTRIDE + lc),
                   &g_x8[(size_t)(bm + lr) * FEAT + k0 + lc]);
        cp_async16(abase + (uint32_t)((lr + 64) * RSTRIDE + lc),
                   &g_x8[(size_t)(bm + lr + 64) * FEAT + k0 + lc]);
        cp_async16(bbase + (uint32_t)(lr * RSTRIDE + lc),
                   &g_w8[(size_t)(bn + lr) * FEAT + k0 + lc]);
        cp_async16(bbase + (uint32_t)((lr + 64) * RSTRIDE + lc),
                   &g_w8[(size_t)(bn + lr + 64) * FEAT + k0 + lc]);
    };

    load_tiles(0, 0);
    CP_COMMIT();
    load_tiles(BKT, 1);
    CP_COMMIT();

    const int NITER = FEAT / BKT;   // 32
    int slot = 0;
    for (int it = 0; it < NITER; it++) {
        CP_WAIT1();
        __syncthreads();

        if (it + 2 < NITER) {
            int ps = slot - 1; if (ps < 0) ps += NSTAGE;
            load_tiles((it + 2) * BKT, ps);
        }
        CP_COMMIT();

        const uint32_t abase = a_smem0 + slot * A_STAGE_BYTES;
        const uint32_t bbase = b_smem0 + slot * B_STAGE_BYTES;

#pragma unroll
        for (int kk = 0; kk < 2; kk++) {   // two k32 steps inside BK=64
            uint32_t afr[2][4];
            uint32_t bfr[8][2];
            // A fragments: m0=rows0-7/bytes lo16, m1=rows8-15/lo, m2/m3=hi16
#pragma unroll
            for (int mt = 0; mt < 2; mt++) {
                int row = wm + mt * 16 + (lane & 15);
                uint32_t addr = abase + (uint32_t)(row * RSTRIDE
                                + kk * 32 + (lane >> 4) * 16);
                asm volatile(
                    "ldmatrix.sync.aligned.m8n8.x4.shared.b16 {%0,%1,%2,%3}, [%4];"
                    : "=r"(afr[mt][0]), "=r"(afr[mt][1]),
                      "=r"(afr[mt][2]), "=r"(afr[mt][3])
                    : "r"(addr));
            }
            // B fragments: x4 covers two n8-groups:
            // m0 = n0-7/k lo16, m1 = n0-7/k hi16, m2 = n8-15/lo, m3 = n8-15/hi
#pragma unroll
            for (int ntp = 0; ntp < 4; ntp++) {
                int row = wn + ntp * 16 + ((lane >> 4) & 1) * 8 + (lane & 7);
                uint32_t addr = bbase + (uint32_t)(row * RSTRIDE
                                + kk * 32 + ((lane >> 3) & 1) * 16);
                asm volatile(
                    "ldmatrix.sync.aligned.m8n8.x4.shared.b16 {%0,%1,%2,%3}, [%4];"
                    : "=r"(bfr[2 * ntp][0]),     "=r"(bfr[2 * ntp][1]),
                      "=r"(bfr[2 * ntp + 1][0]), "=r"(bfr[2 * ntp + 1][1])
                    : "r"(addr));
            }
#pragma unroll
            for (int mt = 0; mt < 2; mt++)
#pragma unroll
                for (int nt = 0; nt < 8; nt++)
                    asm volatile(
                        "mma.sync.aligned.m16n8k32.row.col.f32.e4m3.e4m3.f32 "
                        "{%0,%1,%2,%3}, {%4,%5,%6,%7}, {%8,%9}, {%0,%1,%2,%3};"
                        : "+f"(acc[mt][nt][0]), "+f"(acc[mt][nt][1]),
                          "+f"(acc[mt][nt][2]), "+f"(acc[mt][nt][3])
                        : "r"(afr[mt][0]), "r"(afr[mt][1]),
                          "r"(afr[mt][2]), "r"(afr[mt][3]),
                          "r"(bfr[nt][0]), "r"(bfr[nt][1]));
        }
        slot++; if (slot == NSTAGE) slot = 0;
    }

    // ---- epilogue: unscale (1/64) and write fp16 ----
    uint32_t* Mh32 = reinterpret_cast<uint32_t*>(g_Mh);
#pragma unroll
    for (int mt = 0; mt < 2; mt++) {
        int row = bm + wm + mt * 16 + (lane >> 2);
#pragma unroll
        for (int nt = 0; nt < 8; nt++) {
            int col = bn + wn + nt * 8 + (lane & 3) * 2;
            __half2 h0 = __floats2half2_rn(acc[mt][nt][0] * INV_SCALE,
                                           acc[mt][nt][1] * INV_SCALE);
            __half2 h1 = __floats2half2_rn(acc[mt][nt][2] * INV_SCALE,
                                           acc[mt][nt][3] * INV_SCALE);
            Mh32[((size_t)row * NCOL + col) >> 1]       = *reinterpret_cast<uint32_t*>(&h0);
            Mh32[((size_t)(row + 8) * NCOL + col) >> 1] = *reinterpret_cast<uint32_t*>(&h1);
        }
    }
}

// ---------------------------------------------------------------------------
// Kernel 3: pairwise L1 + exp, symmetric halving (measured: part of 94.9us;
// each unordered pair once; exp(-n) credited to both rows, partner via rare
// shared atomicAdd gated on n<25). UNCHANGED from round 10.
// ---------------------------------------------------------------------------
__global__ __launch_bounds__(128) void pairwise_kernel(float* __restrict__ out) {
    __shared__ __align__(16) __half2 s2[8][NKERN];
    __shared__ float s_acc[NKERN];
    const int b = blockIdx.x;
    const int t = threadIdx.x;

    const uint4* src =
        reinterpret_cast<const uint4*>(g_Mh + (size_t)b * NCOL + t * NDIM);
    const uint4 q0 = src[0];
    const uint4 q1 = src[1];
    __half2 mi[8];
    mi[0] = *reinterpret_cast<const __half2*>(&q0.x);
    mi[1] = *reinterpret_cast<const __half2*>(&q0.y);
    mi[2] = *reinterpret_cast<const __half2*>(&q0.z);
    mi[3] = *reinterpret_cast<const __half2*>(&q0.w);
    mi[4] = *reinterpret_cast<const __half2*>(&q1.x);
    mi[5] = *reinterpret_cast<const __half2*>(&q1.y);
    mi[6] = *reinterpret_cast<const __half2*>(&q1.z);
    mi[7] = *reinterpret_cast<const __half2*>(&q1.w);
#pragma unroll
    for (int q = 0; q < 8; q++) s2[q][t] = mi[q];
    s_acc[t] = 0.0f;
    __syncthreads();

    const __half hthr = __float2half(25.0f);
    float acc = 0.0f;

    auto do_pair = [&](int j) {
        __half2 d0 = __habs2(__hsub2(mi[0], s2[0][j]));
        __half2 d1 = __habs2(__hsub2(mi[1], s2[1][j]));
        __half2 d2 = __habs2(__hsub2(mi[2], s2[2][j]));
        __half2 d3 = __habs2(__hsub2(mi[3], s2[3][j]));
        __half2 d4 = __habs2(__hsub2(mi[4], s2[4][j]));
        __half2 d5 = __habs2(__hsub2(mi[5], s2[5][j]));
        __half2 d6 = __habs2(__hsub2(mi[6], s2[6][j]));
        __half2 d7 = __habs2(__hsub2(mi[7], s2[7][j]));
        __half2 s01 = __hadd2(d0, d1);
        __half2 s23 = __hadd2(d2, d3);
        __half2 s45 = __hadd2(d4, d5);
        __half2 s67 = __hadd2(d6, d7);
        __half2 s03 = __hadd2(s01, s23);
        __half2 s47 = __hadd2(s45, s67);
        __half2 n2  = __hadd2(s03, s47);
        __half  n   = __hadd(__low2half(n2), __high2half(n2));
        if (__hlt(n, hthr)) {
            float e = __expf(-__half2float(n));
            acc += e;
            atomicAdd(&s_acc[j], e);
        }
    };

#pragma unroll 4
    for (int r = 1; r < 64; r++)
        do_pair((t + r) & (NKERN - 1));
    if (t < 64)
        do_pair(t + 64);

    __syncthreads();
    out[b * NKERN + t] = 1.0f + acc + s_acc[t];
}

// ---------------------------------------------------------------------------
// Launcher (graph-capturable: kernel launches + attribute set)
// ---------------------------------------------------------------------------
extern "C" void kernel_launch(void* const* d_in, const int* in_sizes, int n_in,
                              void* d_out, int out_size) {
    const float* x = (const float*)d_in[0];   // [2048, 2048]
    const float* W = (const float*)d_in[1];   // [2048, 2048]
    float* out = (float*)d_out;               // [2048, 128]

    cudaFuncSetAttribute(gemm_kernel,
                         cudaFuncAttributeMaxDynamicSharedMemorySize, GEMM_SMEM);

    cvt_x_kernel<<<1024, 256>>>(x);                      // 16 elems/thread
    cvt_wt_kernel<<<dim3(64, 16), 256>>>(W);             // transpose-quantize

    dim3 grid(NCOL / BN, BATCH / BM);                    // 16 x 16
    gemm_kernel<<<grid, 256, GEMM_SMEM>>>();

    pairwise_kernel<<<BATCH, 128>>>(out);
}